// round 12
// baseline (speedup 1.0000x reference)
#include <cuda_runtime.h>

// out[b,i,n] = sum_j w[i,j] * x[b,j,n]
// x: [256, 3, 65536] fp32, w: [3,3] fp32, out: [256, 3, 65536] fp32
//
// v7: single-wave persistent grid-stride. The problem is pinned at the
// LTS/L2 fabric ceiling (~6300 B/cyc path-independent => ~6.34 TB/s
// sustained; 402.6 MB compulsory per iteration => ~63.5us). This variant
// tests the one remaining structural lever: eliminating ~14 waves of CTA
// launch/retire churn by running 1184 long-lived blocks (148 SMs x 8,
// same occupancy as the best short-block variants) that stride the full
// index space. Loads default policy (best measured), stores write-through
// (best measured).

static constexpr int N_COLS  = 65536;
static constexpr int N4      = N_COLS / 4;        // 16384 float4 per row
static constexpr int BATCH   = 256;
static constexpr long TOTAL4 = (long)BATCH * N4;  // 4,194,304 positions
static constexpr int TPB     = 256;
static constexpr int NBLK    = 148 * 8;           // single wave at 8 CTA/SM

__global__ __launch_bounds__(TPB) void rot3_kernel_v7(
    const float4* __restrict__ x,
    const float*  __restrict__ w,
    float4* __restrict__ out)
{
    // Broadcast weight loads — registers for the whole lifetime.
    float w00 = __ldg(w + 0), w01 = __ldg(w + 1), w02 = __ldg(w + 2);
    float w10 = __ldg(w + 3), w11 = __ldg(w + 4), w12 = __ldg(w + 5);
    float w20 = __ldg(w + 6), w21 = __ldg(w + 7), w22 = __ldg(w + 8);

    const long stride = (long)NBLK * TPB;  // 303,104
    for (long idx = (long)blockIdx.x * TPB + threadIdx.x;
         idx < TOTAL4; idx += stride) {

        int b = (int)(idx >> 14);        // idx / N4
        int n = (int)(idx & (N4 - 1));   // idx % N4

        const float4* xb = x + (size_t)b * 3 * N4;
        float4 x0 = __ldg(xb + n);
        float4 x1 = __ldg(xb + N4 + n);
        float4 x2 = __ldg(xb + 2 * N4 + n);

        float4 o0, o1, o2;
        o0.x = w00*x0.x + w01*x1.x + w02*x2.x;
        o0.y = w00*x0.y + w01*x1.y + w02*x2.y;
        o0.z = w00*x0.z + w01*x1.z + w02*x2.z;
        o0.w = w00*x0.w + w01*x1.w + w02*x2.w;

        o1.x = w10*x0.x + w11*x1.x + w12*x2.x;
        o1.y = w10*x0.y + w11*x1.y + w12*x2.y;
        o1.z = w10*x0.z + w11*x1.z + w12*x2.z;
        o1.w = w10*x0.w + w11*x1.w + w12*x2.w;

        o2.x = w20*x0.x + w21*x1.x + w22*x2.x;
        o2.y = w20*x0.y + w21*x1.y + w22*x2.y;
        o2.z = w20*x0.z + w21*x1.z + w22*x2.z;
        o2.w = w20*x0.w + w21*x1.w + w22*x2.w;

        float4* ob = out + (size_t)b * 3 * N4;
        __stwt(ob + n,          o0);
        __stwt(ob + N4 + n,     o1);
        __stwt(ob + 2 * N4 + n, o2);
    }
}

extern "C" void kernel_launch(void* const* d_in, const int* in_sizes, int n_in,
                              void* d_out, int out_size)
{
    const float4* x = (const float4*)d_in[0];
    const float*  w = (const float*)d_in[1];
    float4* out = (float4*)d_out;

    rot3_kernel_v7<<<NBLK, TPB>>>(x, w, out);
}

// round 13
// speedup vs baseline: 1.1600x; 1.1600x over previous
#include <cuda_runtime.h>

// out[b,i,n] = sum_j w[i,j] * x[b,j,n]
// x: [256, 3, 65536] fp32, w: [3,3] fp32, out: [256, 3, 65536] fp32
//
// FINAL (converged): pure HBM/LTS-bound streamer at the chip's
// path-independent L2-fabric ceiling (~6300 B/cyc => ~6.34 TB/s sustained).
// 402.6 MB compulsory traffic per iteration => ~63.5us period. Measured
// best configuration across 9 variants:
//   - 1 float4 position per thread (3x LDG.128 front-batched, MLP_p1=3)
//   - default-policy loads (beat .cs/.cg/evict_last in every test)
//   - write-through stores (__stwt): no dirty-L2 drain at replay boundary
//   - 16384 blocks x 256 threads: many short blocks keep L1tex queues full
// Rejected by measurement: VPT=2/4 batching, L2 evict_last cross-replay
// residency (x2), persistent grid-stride (-17%).

static constexpr int N_COLS   = 65536;
static constexpr int N4       = N_COLS / 4;        // 16384 float4 per row
static constexpr int BATCH    = 256;
static constexpr long TOTAL4  = (long)BATCH * N4;  // 4,194,304 threads

__global__ __launch_bounds__(256) void rot3_kernel_final(
    const float4* __restrict__ x,
    const float*  __restrict__ w,
    float4* __restrict__ out)
{
    long idx = (long)blockIdx.x * blockDim.x + threadIdx.x;
    if (idx >= TOTAL4) return;

    int b = (int)(idx >> 14);        // idx / N4
    int n = (int)(idx & (N4 - 1));   // idx % N4

    // Broadcast weight loads — L1-resident after first warp.
    float w00 = __ldg(w + 0), w01 = __ldg(w + 1), w02 = __ldg(w + 2);
    float w10 = __ldg(w + 3), w11 = __ldg(w + 4), w12 = __ldg(w + 5);
    float w20 = __ldg(w + 6), w21 = __ldg(w + 7), w22 = __ldg(w + 8);

    const float4* xb = x + (size_t)b * 3 * N4;
    float4 x0 = __ldg(xb + n);
    float4 x1 = __ldg(xb + N4 + n);
    float4 x2 = __ldg(xb + 2 * N4 + n);

    float4 o0, o1, o2;
    o0.x = w00 * x0.x + w01 * x1.x + w02 * x2.x;
    o0.y = w00 * x0.y + w01 * x1.y + w02 * x2.y;
    o0.z = w00 * x0.z + w01 * x1.z + w02 * x2.z;
    o0.w = w00 * x0.w + w01 * x1.w + w02 * x2.w;

    o1.x = w10 * x0.x + w11 * x1.x + w12 * x2.x;
    o1.y = w10 * x0.y + w11 * x1.y + w12 * x2.y;
    o1.z = w10 * x0.z + w11 * x1.z + w12 * x2.z;
    o1.w = w10 * x0.w + w11 * x1.w + w12 * x2.w;

    o2.x = w20 * x0.x + w21 * x1.x + w22 * x2.x;
    o2.y = w20 * x0.y + w21 * x1.y + w22 * x2.y;
    o2.z = w20 * x0.z + w21 * x1.z + w22 * x2.z;
    o2.w = w20 * x0.w + w21 * x1.w + w22 * x2.w;

    float4* ob = out + (size_t)b * 3 * N4;
    __stwt(ob + n,          o0);
    __stwt(ob + N4 + n,     o1);
    __stwt(ob + 2 * N4 + n, o2);
}

extern "C" void kernel_launch(void* const* d_in, const int* in_sizes, int n_in,
                              void* d_out, int out_size)
{
    const float4* x = (const float4*)d_in[0];
    const float*  w = (const float*)d_in[1];
    float4* out = (float4*)d_out;

    const int threads = 256;
    const long blocks = (TOTAL4 + threads - 1) / threads;  // 16384
    rot3_kernel_final<<<(int)blocks, threads>>>(x, w, out);
}